// round 8
// baseline (speedup 1.0000x reference)
#include <cuda_runtime.h>
#include <math.h>

// feat: [B=4, C=256, H=50, W=50] f32;  rois: [R,5] f32;  out: [R,256,7,7] f32
#define BB 4
#define CC 256
#define HH 50
#define WW 50
#define HW 2500
#define PP 7
#define NBIN 49
#define SPATIAL_SCALE 0.0625f
#define MAX_R 512
#define CG 64                    // channels per block
#define NT 256                   // threads per block (8 warps)

// Transposed features: [b][hw][c] — channel-contiguous so warp gathers coalesce.
__device__ __align__(16) float g_featT[BB * HW * CC];
// Packed per-(roi,bin) bounds: ws | we<<8 | hs<<16 | he<<24
__device__ int g_bounds[MAX_R * NBIN];
// Per-roi transposed base offset: b * HW * CC
__device__ int g_base[MAX_R];

__global__ void __launch_bounds__(256)
transpose_kernel(const float* __restrict__ feat) {
    __shared__ float tile[32][33];
    const int b  = blockIdx.z;
    const int c0 = blockIdx.y * 32;
    const int s0 = blockIdx.x * 32;
    const int tx = threadIdx.x;
    const int ty = threadIdx.y;

    #pragma unroll
    for (int j = 0; j < 32; j += 8) {
        int s = s0 + tx;
        if (s < HW)
            tile[ty + j][tx] = feat[((size_t)b * CC + (c0 + ty + j)) * HW + s];
    }
    __syncthreads();
    #pragma unroll
    for (int j = 0; j < 32; j += 8) {
        int s = s0 + ty + j;
        if (s < HW)
            g_featT[((size_t)b * HW + s) * CC + (c0 + tx)] = tile[tx][ty + j];
    }
}

__global__ void roi_setup_kernel(const float* __restrict__ rois) {
    const int r = blockIdx.x;
    const int p = threadIdx.x;           // 0..48
    const float* rp = rois + (size_t)r * 5;

    // jnp.round == round-half-to-even == rintf (RN); *0.0625 exact.
    float x1 = rintf(rp[1] * SPATIAL_SCALE);
    float y1 = rintf(rp[2] * SPATIAL_SCALE);
    float x2 = rintf(rp[3] * SPATIAL_SCALE);
    float y2 = rintf(rp[4] * SPATIAL_SCALE);
    // XLA folds x/7 into x * RN(1/7); replicate exactly.
    const float INV7 = 1.0f / 7.0f;
    float bw = __fmul_rn(fmaxf(x2 - x1 + 1.0f, 1.0f), INV7);
    float bh = __fmul_rn(fmaxf(y2 - y1 + 1.0f, 1.0f), INV7);

    float fpw = (float)(p % PP);
    float fph = (float)(p / PP);

    int ws = (int)fminf(fmaxf(floorf(__fmul_rn(bw, fpw))        + x1, 0.0f), (float)WW);
    int we = (int)fminf(fmaxf(ceilf (__fmul_rn(bw, fpw + 1.0f)) + x1, 0.0f), (float)WW);
    int hs = (int)fminf(fmaxf(floorf(__fmul_rn(bh, fph))        + y1, 0.0f), (float)HH);
    int he = (int)fminf(fmaxf(ceilf (__fmul_rn(bh, fph + 1.0f)) + y1, 0.0f), (float)HH);

    g_bounds[r * NBIN + p] = ws | (we << 8) | (hs << 16) | (he << 24);
    if (p == 0) g_base[r] = (int)rp[0] * (HW * CC);
}

__global__ void __launch_bounds__(NT)
roipool_kernel(float* __restrict__ out) {
    __shared__ float s_out[NBIN][CG + 2];    // [bin][channel], stride 66

    const int r    = blockIdx.x;
    const int cg   = blockIdx.y;             // 64-channel group
    const int t    = threadIdx.x;
    const int lane = t & 31;
    const int wid  = t >> 5;

    // Lane handles 2 channels via float2 (featT is channel-contiguous).
    const float2* fb = (const float2*)(g_featT + __ldg(&g_base[r]) + cg * CG) + lane;
    const int* bp = g_bounds + r * NBIN;

    // Warp `wid` owns bins wid, wid+8, ... — bounds uniform across lanes.
    for (int p = wid; p < NBIN; p += 8) {
        int bnd = __ldg(bp + p);
        int ws =  bnd        & 0xFF;
        int we = (bnd >> 8)  & 0xFF;
        int hs = (bnd >> 16) & 0xFF;
        int he = (bnd >> 24) & 0xFF;

        float m0 = -INFINITY, m1 = -INFINITY;
        for (int h = hs; h < he; ++h) {
            const float2* q = fb + (size_t)(h * WW + ws) * (CC / 2);
            for (int w = ws; w < we; ++w) {
                float2 v = *q;
                m0 = fmaxf(m0, v.x);
                m1 = fmaxf(m1, v.y);
                q += (CC / 2);
            }
        }
        s_out[p][2 * lane]     = (m0 == -INFINITY) ? 0.0f : m0;
        s_out[p][2 * lane + 1] = (m1 == -INFINITY) ? 0.0f : m1;
    }
    __syncthreads();

    // Coalesced writeback: enumerate o = c*49+p; global index = base + o.
    float* ob = out + ((size_t)r * CC + cg * CG) * NBIN;
    #pragma unroll
    for (int i = 0; i < (CG * NBIN + NT - 1) / NT; ++i) {
        int o = t + i * NT;
        if (o < CG * NBIN) {
            int c = o / NBIN;
            int p = o - c * NBIN;
            ob[o] = s_out[p][c];
        }
    }
}

extern "C" void kernel_launch(void* const* d_in, const int* in_sizes, int n_in,
                              void* d_out, int out_size) {
    const float* feat = (const float*)d_in[0];
    const float* rois = (const float*)d_in[1];
    float* out = (float*)d_out;

    int R = in_sizes[1] / 5;   // 128

    dim3 tgrid((HW + 31) / 32, CC / 32, BB);   // 79 x 8 x 4
    dim3 tblk(32, 8);
    transpose_kernel<<<tgrid, tblk>>>(feat);

    roi_setup_kernel<<<R, NBIN>>>(rois);

    dim3 ggrid(R, CC / CG);                    // 128 x 4
    roipool_kernel<<<ggrid, NT>>>(out);
}

// round 10
// speedup vs baseline: 1.1556x; 1.1556x over previous
#include <cuda_runtime.h>
#include <math.h>

// feat: [B=4, C=256, H=50, W=50] f32;  rois: [R,5] f32;  out: [R,256,7,7] f32
#define CC 256
#define HW 2500
#define HH 50
#define WW 50
#define PP 7
#define NBIN 49
#define SPATIAL_SCALE 0.0625f
#define G 32                 // channels per block (one warp-lane per channel)
#define NT 256               // 8 warps
#define RROWS 17             // ROI region provably <= 17 rows/cols
#define RSTRIDE 18
#define SLAB 307             // 17*18+1, odd -> lane*SLAB is a bank permutation

__global__ void __launch_bounds__(NT)
roipool_kernel(const float* __restrict__ feat,
               const float* __restrict__ rois,
               float* __restrict__ out) {
    __shared__ float s_tile[G * SLAB];       // 39,296 B
    __shared__ float s_out[NBIN][G + 1];     // 6,468 B, stride 33 (odd)
    __shared__ int   s_bnd[NBIN];            // ws | we<<8 | hs<<16 | he<<24
    __shared__ int   s_b;

    const int r    = blockIdx.x;
    const int cg   = blockIdx.y;             // 32-channel group
    const int t    = threadIdx.x;
    const int lane = t & 31;
    const int wid  = t >> 5;

    if (t < NBIN) {
        const float* rp = rois + (size_t)r * 5;
        // jnp.round == round-half-to-even == rintf (RN); *0.0625 exact.
        float x1 = rintf(rp[1] * SPATIAL_SCALE);
        float y1 = rintf(rp[2] * SPATIAL_SCALE);
        float x2 = rintf(rp[3] * SPATIAL_SCALE);
        float y2 = rintf(rp[4] * SPATIAL_SCALE);
        // XLA folds x/7 into x * RN(1/7); replicate exactly.
        const float INV7 = 1.0f / 7.0f;
        float bw = __fmul_rn(fmaxf(x2 - x1 + 1.0f, 1.0f), INV7);
        float bh = __fmul_rn(fmaxf(y2 - y1 + 1.0f, 1.0f), INV7);
        float fpw = (float)(t % PP);
        float fph = (float)(t / PP);
        int ws = (int)fminf(fmaxf(floorf(__fmul_rn(bw, fpw))        + x1, 0.0f), (float)WW);
        int we = (int)fminf(fmaxf(ceilf (__fmul_rn(bw, fpw + 1.0f)) + x1, 0.0f), (float)WW);
        int hs = (int)fminf(fmaxf(floorf(__fmul_rn(bh, fph))        + y1, 0.0f), (float)HH);
        int he = (int)fminf(fmaxf(ceilf (__fmul_rn(bh, fph + 1.0f)) + y1, 0.0f), (float)HH);
        s_bnd[t] = ws | (we << 8) | (hs << 16) | (he << 24);
        if (t == 0) s_b = (int)rp[0];
    }
    __syncthreads();

    // Region covering all bins (bounds monotone in p).
    const int b0  = s_bnd[0], b48 = s_bnd[NBIN - 1];
    const int w0  = b0 & 0xFF;
    const int h0  = (b0 >> 16) & 0xFF;
    const int rw  = min(((b48 >> 8)  & 0xFF) - w0, RSTRIDE);  // <= 17
    const int rh  = min(((b48 >> 24) & 0xFF) - h0, RROWS);    // <= 17

    // Load phase: warp `wid` copies channel slabs cl = wid, wid+8, +16, +24.
    // Rows are contiguous gmem (coalesced); bounds uniform per block.
    const float* fbase = feat + ((size_t)(s_b * CC) + cg * G) * HW + h0 * WW + w0;
    #pragma unroll
    for (int k = 0; k < 4; ++k) {
        const int cl = wid + 8 * k;
        const float* fp = fbase + (size_t)cl * HW;
        float* tp = s_tile + cl * SLAB;
        if (lane < rw) {
            for (int hh = 0; hh < rh; ++hh)
                tp[hh * RSTRIDE + lane] = __ldg(fp + hh * WW + lane);
        }
    }
    __syncthreads();

    // Compute phase: warp-round = one bin for 32 channels (lane = channel).
    // Bounds uniform across the warp -> variable loops, zero divergence.
    const float* tp = s_tile + lane * SLAB;
    for (int p = wid; p < NBIN; p += 8) {
        int bnd = s_bnd[p];
        int wsr = ( bnd        & 0xFF) - w0;
        int wer = ((bnd >> 8)  & 0xFF) - w0;
        int hsr = ((bnd >> 16) & 0xFF) - h0;
        int her = ((bnd >> 24) & 0xFF) - h0;

        float m0 = -INFINITY, m1 = -INFINITY;
        for (int h = hsr; h < her; ++h) {
            const float* q = tp + h * RSTRIDE;
            int w = wsr;
            for (; w + 1 < wer; w += 2) {
                m0 = fmaxf(m0, q[w]);
                m1 = fmaxf(m1, q[w + 1]);
            }
            if (w < wer) m0 = fmaxf(m0, q[w]);
        }
        float m = fmaxf(m0, m1);
        s_out[p][lane] = (m == -INFINITY) ? 0.0f : m;   // empty bin -> 0
    }
    __syncthreads();

    // Coalesced writeback: out[r][c0+c][p], o = c*49 + p.
    float* ob = out + ((size_t)r * CC + cg * G) * NBIN;
    #pragma unroll
    for (int i = 0; i < (G * NBIN + NT - 1) / NT; ++i) {
        int o = t + i * NT;
        if (o < G * NBIN) {
            int c = o / NBIN;          // const divisor -> mul/shift
            int p = o - c * NBIN;
            ob[o] = s_out[p][c];       // stride-33 LDS, conflict-free
        }
    }
}

extern "C" void kernel_launch(void* const* d_in, const int* in_sizes, int n_in,
                              void* d_out, int out_size) {
    const float* feat = (const float*)d_in[0];
    const float* rois = (const float*)d_in[1];
    float* out = (float*)d_out;

    int R = in_sizes[1] / 5;                 // 128
    dim3 grid(R, CC / G);                    // 128 x 8 = 1024 blocks
    roipool_kernel<<<grid, NT>>>(feat, rois, out);
}

// round 11
// speedup vs baseline: 1.6930x; 1.4651x over previous
#include <cuda_runtime.h>
#include <math.h>

// feat: [B=4, C=256, H=50, W=50] f32;  rois: [R,5] f32;  out: [R,256,7,7] f32
#define CC 256
#define HW 2500
#define HH 50
#define WW 50
#define PP 7
#define NBIN 49
#define SPATIAL_SCALE 0.0625f
#define MAX_R 512

// Packed per-(roi,bin): (hs*50+ws) in low 12 bits | 16-bit 4x4 validity mask << 16
__device__ int g_tab[MAX_R * NBIN];
// Per-roi feature base offset: b * CC * HW
__device__ int g_base[MAX_R];

__global__ void roi_setup_kernel(const float* __restrict__ rois) {
    const int r = blockIdx.x;
    const int p = threadIdx.x;           // 0..48
    const float* rp = rois + (size_t)r * 5;

    // jnp.round == round-half-to-even == rintf (RN); *0.0625 exact.
    float x1 = rintf(rp[1] * SPATIAL_SCALE);
    float y1 = rintf(rp[2] * SPATIAL_SCALE);
    float x2 = rintf(rp[3] * SPATIAL_SCALE);
    float y2 = rintf(rp[4] * SPATIAL_SCALE);
    // XLA folds x/7 into x * RN(1/7); replicate exactly.
    const float INV7 = 1.0f / 7.0f;
    float bw = __fmul_rn(fmaxf(x2 - x1 + 1.0f, 1.0f), INV7);
    float bh = __fmul_rn(fmaxf(y2 - y1 + 1.0f, 1.0f), INV7);

    float fpw = (float)(p % PP);
    float fph = (float)(p / PP);

    int ws = (int)fminf(fmaxf(floorf(__fmul_rn(bw, fpw))        + x1, 0.0f), (float)WW);
    int we = (int)fminf(fmaxf(ceilf (__fmul_rn(bw, fpw + 1.0f)) + x1, 0.0f), (float)WW);
    int hs = (int)fminf(fmaxf(floorf(__fmul_rn(bh, fph))        + y1, 0.0f), (float)HH);
    int he = (int)fminf(fmaxf(ceilf (__fmul_rn(bh, fph + 1.0f)) + y1, 0.0f), (float)HH);

    int nw = we - ws;                    // 0..4 (window provably <= 4x4)
    int nh = he - hs;                    // 0..4
    // 4x4 validity bitmask: bit (i*4+j) set iff i<nh && j<nw.
    unsigned rowpat = (nw > 0) ? ((1u << nw) - 1u) : 0u;
    unsigned rows   = (nh > 0) ? (0x1111u & ((1u << (4 * nh)) - 1u)) : 0u;
    unsigned mask   = rowpat * rows;

    g_tab[r * NBIN + p] = (hs * WW + ws) | ((int)mask << 16);
    if (p == 0) g_base[r] = (int)rp[0] * (CC * HW);
}

__global__ void __launch_bounds__(256)
roipool_kernel(const float* __restrict__ feat,
               float* __restrict__ out, int total) {
    int idx = blockIdx.x * blockDim.x + threadIdx.x;
    if (idx >= total) return;

    int p  = idx % NBIN;
    int rc = idx / NBIN;            // r*256 + c
    int r  = rc >> 8;
    int c  = rc & 255;

    int tab = __ldg(&g_tab[r * NBIN + p]);
    unsigned mask = ((unsigned)tab) >> 16;
    int off = tab & 0xFFF;

    const float* base = feat + __ldg(&g_base[r]) + c * HW + off;

    // 16 predicated loads at compile-time-constant offsets; predicated-off
    // lanes generate no L1 traffic. Four independent accumulators (ILP).
    float m0 = -INFINITY, m1 = -INFINITY, m2 = -INFINITY, m3 = -INFINITY;
    #pragma unroll
    for (int i = 0; i < 4; ++i) {
        {
            float v = -INFINITY;
            if (mask & (1u << (i * 4 + 0))) v = __ldg(base + i * WW + 0);
            m0 = fmaxf(m0, v);
        }
        {
            float v = -INFINITY;
            if (mask & (1u << (i * 4 + 1))) v = __ldg(base + i * WW + 1);
            m1 = fmaxf(m1, v);
        }
        {
            float v = -INFINITY;
            if (mask & (1u << (i * 4 + 2))) v = __ldg(base + i * WW + 2);
            m2 = fmaxf(m2, v);
        }
        {
            float v = -INFINITY;
            if (mask & (1u << (i * 4 + 3))) v = __ldg(base + i * WW + 3);
            m3 = fmaxf(m3, v);
        }
    }
    float m = fmaxf(fmaxf(m0, m1), fmaxf(m2, m3));
    out[idx] = (m == -INFINITY) ? 0.0f : m;
}

extern "C" void kernel_launch(void* const* d_in, const int* in_sizes, int n_in,
                              void* d_out, int out_size) {
    const float* feat = (const float*)d_in[0];
    const float* rois = (const float*)d_in[1];
    float* out = (float*)d_out;

    int R = in_sizes[1] / 5;           // 128
    int total = R * CC * NBIN;         // 1,605,632

    roi_setup_kernel<<<R, NBIN>>>(rois);

    int threads = 256;
    int blocks = (total + threads - 1) / threads;
    roipool_kernel<<<blocks, threads>>>(feat, out, total);
}